// round 4
// baseline (speedup 1.0000x reference)
#include <cuda_runtime.h>
#include <cstdint>

// Problem dims (fixed): B=4, T=4096, D_IN=1024, H=16, D=64
#define TB 4
#define TT 4096
#define TDIN 1024
#define TH 16
#define TD 64
#define NC 64     // chunks per (b,h)
#define CT 64     // timesteps per chunk

// ---------------- scratch ----------------------------------------------------
__device__ float g_Wc[1024ull * 2048];      // tf32(RNA)-rounded W [k][n]  ( 8 MB)
__device__ float g_V [64ull * 64 * 4096];   // v[bh][d][t]                 (64 MB)
__device__ float g_S [64ull * 4096];        // s[bh][t]                    ( 1 MB)
__device__ float g_E [64 * NC];             // chunk e-sums -> excl prefix
__device__ float g_W [64ull * NC * TD];     // chunk e*v sums -> excl prefix

// ---------------- kernel 0: round W to tf32 (RNA), same layout --------------
__global__ void cvt_w_kernel(const float4* __restrict__ in)
{
    int i = blockIdx.x * blockDim.x + threadIdx.x;   // 524288 float4s
    float4 v = in[i];
    uint32_t r;
    asm("cvt.rna.tf32.f32 %0, %1;" : "=r"(r) : "f"(v.x)); v.x = __uint_as_float(r);
    asm("cvt.rna.tf32.f32 %0, %1;" : "=r"(r) : "f"(v.y)); v.y = __uint_as_float(r);
    asm("cvt.rna.tf32.f32 %0, %1;" : "=r"(r) : "f"(v.z)); v.z = __uint_as_float(r);
    asm("cvt.rna.tf32.f32 %0, %1;" : "=r"(r) : "f"(v.w)); v.w = __uint_as_float(r);
    ((float4*)g_Wc)[i] = v;
}

// ---------------- kernel 1: tf32 GEMM (BM=128,BN=256,BK=32) + epilogue ------
// 256 threads = 8 warps in 2(M) x 4(N); warp tile 64x64; thread 8x16 accs.
// A read straight from X (HW tf32-truncates A); B from RNA-rounded g_Wc.
// 3 cp.async stages. smem floats:
//   [0,128)    q (2 heads x 64)
//   [128,640)  spart [head][part][128 rows]
//   [1024 + st*12544): A 128x32 (XOR-swizzled), then B 32x264 (8-pad pitch)
#define STGF 12544           // floats per stage
#define TILEF 1024           // tiles start (floats)

__global__ __launch_bounds__(256, 1)
void gemm_kernel(const float* __restrict__ X, const float* __restrict__ Qk)
{
    extern __shared__ float smem[];
    const uint32_t sb = (uint32_t)__cvta_generic_to_shared(smem);
    const int tid = threadIdx.x, warp = tid >> 5, lane = tid & 31;
    const int nt = blockIdx.x;               // 0..7  (heads 2nt, 2nt+1)
    const int mt = blockIdx.y;               // 0..127
    const int m0 = mt << 7, n0 = nt << 8;

    // ---- copy plans (per stage: A 4x16B, B 8x16B per thread) ----
    uint32_t aoffb[4]; const float* agp[4];
#pragma unroll
    for (int i = 0; i < 4; i++) {
        int g = tid + i * 256, row = g >> 3, c4 = g & 7;
        aoffb[i] = row * 128 + ((c4 ^ (row & 7)) << 4);      // bytes in A tile
        agp[i]   = X + (size_t)(m0 + row) * TDIN + c4 * 4;
    }
    uint32_t boffb[8]; const float* bgp[8];
#pragma unroll
    for (int i = 0; i < 8; i++) {
        int g = tid + i * 256, row = g >> 6, c = g & 63;
        boffb[i] = 16384 + row * 1056 + c * 16;              // bytes (A=16KB first)
        bgp[i]   = g_Wc + (size_t)row * 2048 + n0 + c * 4;
    }
    auto load_stage = [&](int st, int k0) {
        uint32_t base = sb + 4096 + st * (STGF * 4);
#pragma unroll
        for (int i = 0; i < 4; i++)
            asm volatile("cp.async.cg.shared.global [%0], [%1], 16;"
                         :: "r"(base + aoffb[i]), "l"(agp[i] + k0) : "memory");
#pragma unroll
        for (int i = 0; i < 8; i++)
            asm volatile("cp.async.cg.shared.global [%0], [%1], 16;"
                         :: "r"(base + boffb[i]), "l"(bgp[i] + (size_t)k0 * 2048) : "memory");
        asm volatile("cp.async.commit_group;" ::: "memory");
    };

    load_stage(0, 0);
    load_stage(1, 32);
    if (tid < 128) smem[tid] = Qk[(nt << 7) + tid];

    // fragment addressing
    const int wm = (warp >> 2) << 6;         // 0/64
    const int wc = warp & 3;                 // n quarter
    const int arow = wm + (lane & 15);
    const int akhi = lane >> 4, asw = arow & 7;
    const int bk = lane & 3, bn = (wc << 6) + (lane >> 2);

    float acc[4][8][4];
#pragma unroll
    for (int a = 0; a < 4; a++)
#pragma unroll
        for (int b = 0; b < 8; b++)
#pragma unroll
            for (int c = 0; c < 4; c++) acc[a][b][c] = 0.f;

    for (int kt = 0; kt < 32; kt++) {
        if (kt < 31) asm volatile("cp.async.wait_group 1;" ::: "memory");
        else         asm volatile("cp.async.wait_group 0;" ::: "memory");
        __syncthreads();
        if (kt + 2 < 32) load_stage((kt + 2) % 3, (kt + 2) << 5);

        const int cs = kt % 3;
        const uint32_t ab = sb + 4096 + cs * (STGF * 4);
        const float* Bu = smem + TILEF + cs * STGF + 4096 + bk * 264 + bn;

#pragma unroll
        for (int ks = 0; ks < 4; ks++) {
            uint32_t afr[4][4];
#pragma unroll
            for (int mi = 0; mi < 4; mi++) {
                uint32_t addr = ab + 4u * ((arow + mi * 16) * 32 +
                                           ((((ks << 1) + akhi) ^ asw) << 2));
                asm volatile("ldmatrix.sync.aligned.m8n8.x4.shared.b16 {%0,%1,%2,%3}, [%4];"
                             : "=r"(afr[mi][0]), "=r"(afr[mi][1]),
                               "=r"(afr[mi][2]), "=r"(afr[mi][3]) : "r"(addr));
            }
            uint32_t bfr[8][2];
#pragma unroll
            for (int ni = 0; ni < 8; ni++) {
                const float* bp = Bu + (ks * 8) * 264 + ni * 8;
                bfr[ni][0] = __float_as_uint(bp[0]);
                bfr[ni][1] = __float_as_uint(bp[4 * 264]);
            }
#pragma unroll
            for (int mi = 0; mi < 4; mi++)
#pragma unroll
                for (int ni = 0; ni < 8; ni++) {
                    asm volatile("mma.sync.aligned.m16n8k8.row.col.f32.tf32.tf32.f32 "
                                 "{%0,%1,%2,%3}, {%4,%5,%6,%7}, {%8,%9}, {%0,%1,%2,%3};"
                                 : "+f"(acc[mi][ni][0]), "+f"(acc[mi][ni][1]),
                                   "+f"(acc[mi][ni][2]), "+f"(acc[mi][ni][3])
                                 : "r"(afr[mi][0]), "r"(afr[mi][1]),
                                   "r"(afr[mi][2]), "r"(afr[mi][3]),
                                   "r"(bfr[ni][0]), "r"(bfr[ni][1]));
                }
        }
    }

    // ---- epilogue: relu, V store [bh][d][t], s = sum_d q*relu(k) ----
    const int head = wc >> 1, hp = wc & 1;
    const int b = m0 >> 12, t0 = m0 & (TT - 1);
    const int bh = b * TH + nt * 2 + head;
    const float* qh = smem + head * 64;
    float* vbase = g_V + (size_t)bh * (64 * 4096);

#pragma unroll
    for (int mi = 0; mi < 4; mi++) {
#pragma unroll
        for (int hf = 0; hf < 2; hf++) {
            float sp = 0.f;
            const int row = wm + mi * 16 + (lane >> 2) + hf * 8;
#pragma unroll
            for (int ni = 0; ni < 8; ni++) {
                const int d = hp * 32 + ni * 4 + (lane & 3);
                float kk = fmaxf(acc[mi][ni][hf * 2], 0.f);
                float vv = fmaxf(acc[mi][ni][hf * 2 + 1], 0.f);
                sp = fmaf(qh[d], kk, sp);
                vbase[(size_t)d * 4096 + t0 + row] = vv;
            }
            sp += __shfl_xor_sync(0xffffffffu, sp, 1);
            sp += __shfl_xor_sync(0xffffffffu, sp, 2);
            if ((lane & 3) == 0) smem[128 + (head * 2 + hp) * 128 + row] = sp;
        }
    }
    __syncthreads();
    if (tid < 256) {
        const int hd = tid >> 7, row = tid & 127;
        float s = smem[128 + (hd * 2 + 0) * 128 + row]
                + smem[128 + (hd * 2 + 1) * 128 + row];
        g_S[(size_t)(b * TH + nt * 2 + hd) * TT + t0 + row] = s;
    }
}

// ---------------- kernel 2a: chunk partial sums E, W[d] ---------------------
__global__ void partial_kernel()
{
    const int ch = blockIdx.x, bh = blockIdx.y, tid = threadIdx.x;   // 64 thr
    __shared__ float es[CT];
    __shared__ float ws[2];
    const float* sp = g_S + (size_t)bh * TT + ch * CT;
    float e = __expf(sp[tid]);
    es[tid] = e;
    float se = e;
#pragma unroll
    for (int o = 16; o; o >>= 1) se += __shfl_xor_sync(0xffffffffu, se, o);
    if ((tid & 31) == 0) ws[tid >> 5] = se;
    __syncthreads();
    if (tid == 0) g_E[bh * NC + ch] = ws[0] + ws[1];

    const float4* vp4 = (const float4*)(g_V + ((size_t)bh * 64 + tid) * 4096 + ch * CT);
    float w = 0.f;
#pragma unroll
    for (int j = 0; j < 16; j++) {
        float4 v = vp4[j];
        w = fmaf(es[4 * j],     v.x, w);
        w = fmaf(es[4 * j + 1], v.y, w);
        w = fmaf(es[4 * j + 2], v.z, w);
        w = fmaf(es[4 * j + 3], v.w, w);
    }
    g_W[((size_t)bh * NC + ch) * TD + tid] = w;
}

// ---------------- kernel 2b: exclusive scan of chunk aggregates -------------
__global__ void scanagg_kernel()
{
    const int bh = blockIdx.x, d = threadIdx.x;      // 64 threads
    float* wp = g_W + (size_t)bh * NC * TD + d;
    float aw = 0.f;
    for (int c = 0; c < NC; c++) {
        float t = wp[(size_t)c * TD];
        wp[(size_t)c * TD] = aw;
        aw += t;
    }
    if (d == 0) {
        float* ep = g_E + bh * NC;
        float ae = 0.f;
        for (int c = 0; c < NC; c++) { float t = ep[c]; ep[c] = ae; ae += t; }
    }
}

// ---------------- kernel 2c: local scan + head-sum -> out -------------------
// Block = (chunk, batch), 1024 threads. Phase A: tid=(h,t) exp+prefix -> rc.
// Phase B: tid=(h,d) runs the chain; every 4 steps reduce over h into out.
__global__ __launch_bounds__(1024) void final_kernel(float* __restrict__ out)
{
    __shared__ float es_s[1024], rc_s[1024], p_s[16 * 4 * 64], wtot[16];
    const int ch = blockIdx.x, b = blockIdx.y, tid = threadIdx.x;
    const int h = tid >> 6, t = tid & 63, lane = tid & 31, uh = (tid >> 5) & 1;
    const int bh = b * TH + h;

    float e = __expf(g_S[(size_t)bh * TT + ch * CT + t]);
    es_s[tid] = e;
    float p = e;
#pragma unroll
    for (int o = 1; o < 32; o <<= 1) {
        float x = __shfl_up_sync(0xffffffffu, p, o);
        if (lane >= o) p += x;
    }
    if (lane == 31 && uh == 0) wtot[h] = p;
    __syncthreads();
    float pref = p + (uh ? wtot[h] : 0.f);
    rc_s[tid] = 1.0f / (g_E[bh * NC + ch] + pref);
    __syncthreads();

    const int d = t;                                 // phase B mapping
    float a = g_W[((size_t)bh * NC + ch) * TD + d];  // exclusive prefix
    const float4* vp4 = (const float4*)(g_V + ((size_t)bh * 64 + d) * 4096 + ch * CT);
    float* outb = out + ((size_t)b * TT + ch * CT) * TD;

    for (int g4 = 0; g4 < 16; g4++) {
        float4 v = vp4[g4];
        a = fmaf(es_s[h * 64 + g4 * 4 + 0], v.x, a);
        p_s[(h * 4 + 0) * 64 + d] = a * rc_s[h * 64 + g4 * 4 + 0];
        a = fmaf(es_s[h * 64 + g4 * 4 + 1], v.y, a);
        p_s[(h * 4 + 1) * 64 + d] = a * rc_s[h * 64 + g4 * 4 + 1];
        a = fmaf(es_s[h * 64 + g4 * 4 + 2], v.z, a);
        p_s[(h * 4 + 2) * 64 + d] = a * rc_s[h * 64 + g4 * 4 + 2];
        a = fmaf(es_s[h * 64 + g4 * 4 + 3], v.w, a);
        p_s[(h * 4 + 3) * 64 + d] = a * rc_s[h * 64 + g4 * 4 + 3];
        __syncthreads();
        if (tid < 256) {
            int tt = tid >> 6, dd = tid & 63;
            float s = 0.f;
#pragma unroll
            for (int hh = 0; hh < 16; hh++) s += p_s[(hh * 4 + tt) * 64 + dd];
            outb[(size_t)(g4 * 4 + tt) * TD + dd] = s;
        }
        __syncthreads();
    }
}

// ---------------- launch ----------------------------------------------------
extern "C" void kernel_launch(void* const* d_in, const int* in_sizes, int n_in,
                              void* d_out, int out_size)
{
    const float* x = (const float*)d_in[0];   // inputs    [4,4096,1024]
    const float* w = (const float*)d_in[1];   // kv_kernel [1024,16,64,2]
    const float* q = (const float*)d_in[2];   // q_kernel  [16,64]
    float* out = (float*)d_out;               // [4,4096,64] f32

    cvt_w_kernel<<<2048, 256>>>((const float4*)w);

    cudaFuncSetAttribute(gemm_kernel,
                         cudaFuncAttributeMaxDynamicSharedMemorySize, 154624);
    gemm_kernel<<<dim3(8, 128), 256, 154624>>>(x, q);

    partial_kernel<<<dim3(NC, 64), CT>>>();
    scanagg_kernel<<<64, TD>>>();
    final_kernel<<<dim3(NC, TB), 1024>>>(out);
}

// round 5
// speedup vs baseline: 1.0641x; 1.0641x over previous
#include <cuda_runtime.h>
#include <cstdint>

// Problem dims (fixed): B=4, T=4096, D_IN=1024, H=16, D=64
#define TB 4
#define TT 4096
#define TDIN 1024
#define TH 16
#define TD 64
#define NC 64     // chunks per (b,h)
#define CT 64     // timesteps per chunk

// ---------------- scratch ----------------------------------------------------
__device__ float g_Wc[1024ull * 2048];      // tf32(RNA)-rounded W [k][n]  ( 8 MB)
__device__ float g_V [64ull * 64 * 4096];   // v[bh][d][t]                 (64 MB)
__device__ float g_S [64ull * 4096];        // s[bh][t]                    ( 1 MB)
__device__ float g_E [64 * NC];             // chunk e-sums -> excl prefix
__device__ float g_W [64ull * NC * TD];     // chunk e*v sums -> excl prefix

// ---------------- kernel 0: round W to tf32 (RNA), same layout --------------
__global__ void cvt_w_kernel(const float4* __restrict__ in)
{
    int i = blockIdx.x * blockDim.x + threadIdx.x;   // 524288 float4s
    float4 v = in[i];
    uint32_t r;
    asm("cvt.rna.tf32.f32 %0, %1;" : "=r"(r) : "f"(v.x)); v.x = __uint_as_float(r);
    asm("cvt.rna.tf32.f32 %0, %1;" : "=r"(r) : "f"(v.y)); v.y = __uint_as_float(r);
    asm("cvt.rna.tf32.f32 %0, %1;" : "=r"(r) : "f"(v.z)); v.z = __uint_as_float(r);
    asm("cvt.rna.tf32.f32 %0, %1;" : "=r"(r) : "f"(v.w)); v.w = __uint_as_float(r);
    ((float4*)g_Wc)[i] = v;
}

// ---------------- kernel 1: tf32 GEMM (BM=256,BN=128,BK=32) + epilogue ------
// 512 threads = 16 warps in 4(M) x 4(N); warp tile 64x32; thread 4x4x4 accs.
// A read straight from X (HW tf32-truncates A); B from RNA-rounded g_Wc.
// 3 cp.async stages. smem floats:
//   [0,64)     q (1 head x 64)
//   [64,1088)  spart [4 n-warps][256 rows]
//   tiles @ byte 5120 + st*50176: A 256x32 (XOR-swizzled, 32KB),
//                                 B 32x136-pitch (17408B)
#define STGB 50176           // bytes per stage
#define TILEB 5120           // tiles start (bytes)

__global__ __launch_bounds__(512, 1)
void gemm_kernel(const float* __restrict__ X, const float* __restrict__ Qk)
{
    extern __shared__ float smem[];
    const uint32_t sb = (uint32_t)__cvta_generic_to_shared(smem);
    const int tid = threadIdx.x, warp = tid >> 5, lane = tid & 31;
    const int nt = blockIdx.x;               // 0..15 (head)
    const int mt = blockIdx.y;               // 0..63
    const int m0 = mt << 8, n0 = nt << 7;

    // ---- copy plans (per stage: A 4x16B, B 2x16B per thread) ----
    uint32_t aoffb[4]; const float* agp[4];
#pragma unroll
    for (int i = 0; i < 4; i++) {
        int g = tid + i * 512, row = g >> 3, c4 = g & 7;   // 256 rows x 8 f4
        aoffb[i] = row * 128 + ((c4 ^ (row & 7)) << 4);
        agp[i]   = X + (size_t)(m0 + row) * TDIN + c4 * 4;
    }
    uint32_t boffb[2]; const float* bgp[2];
#pragma unroll
    for (int i = 0; i < 2; i++) {
        int g = tid + i * 512, row = g >> 5, c4 = g & 31;  // 32 rows x 32 f4
        boffb[i] = 32768 + row * 544 + c4 * 16;
        bgp[i]   = g_Wc + (size_t)row * 2048 + n0 + c4 * 4;
    }
    auto load_stage = [&](int st, int k0) {
        uint32_t base = sb + TILEB + st * STGB;
#pragma unroll
        for (int i = 0; i < 4; i++)
            asm volatile("cp.async.cg.shared.global [%0], [%1], 16;"
                         :: "r"(base + aoffb[i]), "l"(agp[i] + k0) : "memory");
#pragma unroll
        for (int i = 0; i < 2; i++)
            asm volatile("cp.async.cg.shared.global [%0], [%1], 16;"
                         :: "r"(base + boffb[i]), "l"(bgp[i] + (size_t)k0 * 2048) : "memory");
        asm volatile("cp.async.commit_group;" ::: "memory");
    };

    load_stage(0, 0);
    load_stage(1, 32);
    if (tid < 64) smem[tid] = Qk[(nt << 6) + tid];

    // fragment addressing (R2-proven warp-tile mapping, wm now 4 quarters)
    const int wm = (warp >> 2) << 6;         // 0/64/128/192
    const int wc = warp & 3;                 // n quarter (32 floats)
    const int arow = wm + (lane & 15);
    const int akhi = lane >> 4, asw = arow & 7;
    const int bk = lane & 3, bn = (wc << 5) + (lane >> 2);

    float acc[4][4][4];
#pragma unroll
    for (int a = 0; a < 4; a++)
#pragma unroll
        for (int b = 0; b < 4; b++)
#pragma unroll
            for (int c = 0; c < 4; c++) acc[a][b][c] = 0.f;

    for (int kt = 0; kt < 32; kt++) {
        if (kt < 31) asm volatile("cp.async.wait_group 1;" ::: "memory");
        else         asm volatile("cp.async.wait_group 0;" ::: "memory");
        __syncthreads();
        if (kt + 2 < 32) load_stage((kt + 2) % 3, (kt + 2) << 5);

        const int cs = kt % 3;
        const uint32_t ab = sb + TILEB + cs * STGB;
        const float* Bu = (const float*)((const char*)smem + TILEB + cs * STGB + 32768)
                        + bk * 136 + bn;

#pragma unroll
        for (int ks = 0; ks < 4; ks++) {
            uint32_t afr[4][4];
#pragma unroll
            for (int mi = 0; mi < 4; mi++) {
                uint32_t addr = ab + 4u * ((arow + mi * 16) * 32 +
                                           ((((ks << 1) + akhi) ^ asw) << 2));
                asm volatile("ldmatrix.sync.aligned.m8n8.x4.shared.b16 {%0,%1,%2,%3}, [%4];"
                             : "=r"(afr[mi][0]), "=r"(afr[mi][1]),
                               "=r"(afr[mi][2]), "=r"(afr[mi][3]) : "r"(addr));
            }
            uint32_t bfr[4][2];
#pragma unroll
            for (int ni = 0; ni < 4; ni++) {
                const float* bp = Bu + (ks * 8) * 136 + ni * 8;
                bfr[ni][0] = __float_as_uint(bp[0]);
                bfr[ni][1] = __float_as_uint(bp[4 * 136]);
            }
#pragma unroll
            for (int mi = 0; mi < 4; mi++)
#pragma unroll
                for (int ni = 0; ni < 4; ni++) {
                    asm volatile("mma.sync.aligned.m16n8k8.row.col.f32.tf32.tf32.f32 "
                                 "{%0,%1,%2,%3}, {%4,%5,%6,%7}, {%8,%9}, {%0,%1,%2,%3};"
                                 : "+f"(acc[mi][ni][0]), "+f"(acc[mi][ni][1]),
                                   "+f"(acc[mi][ni][2]), "+f"(acc[mi][ni][3])
                                 : "r"(afr[mi][0]), "r"(afr[mi][1]),
                                   "r"(afr[mi][2]), "r"(afr[mi][3]),
                                   "r"(bfr[ni][0]), "r"(bfr[ni][1]));
                }
        }
    }

    // ---- epilogue: relu, V store [bh][d][t], s = sum_d q*relu(k) ----
    const int b = m0 >> 12, t0 = m0 & (TT - 1);
    const int bh = b * TH + nt;
    const int d0 = (wc << 4) + (lane & 3);
    float qv[4];
#pragma unroll
    for (int ni = 0; ni < 4; ni++) qv[ni] = smem[d0 + ni * 4];
    float* vbase = g_V + (size_t)bh * (64 * 4096);

#pragma unroll
    for (int mi = 0; mi < 4; mi++) {
#pragma unroll
        for (int hf = 0; hf < 2; hf++) {
            float sp = 0.f;
            const int row = wm + mi * 16 + (lane >> 2) + hf * 8;
#pragma unroll
            for (int ni = 0; ni < 4; ni++) {
                const int d = d0 + ni * 4;
                float kk = fmaxf(acc[mi][ni][hf * 2], 0.f);
                float vv = fmaxf(acc[mi][ni][hf * 2 + 1], 0.f);
                sp = fmaf(qv[ni], kk, sp);
                vbase[(size_t)d * 4096 + t0 + row] = vv;
            }
            sp += __shfl_xor_sync(0xffffffffu, sp, 1);
            sp += __shfl_xor_sync(0xffffffffu, sp, 2);
            if ((lane & 3) == 0) smem[64 + wc * 256 + row] = sp;
        }
    }
    __syncthreads();
    if (tid < 256) {
        float s = smem[64 + tid] + smem[64 + 256 + tid]
                + smem[64 + 512 + tid] + smem[64 + 768 + tid];
        g_S[(size_t)bh * TT + t0 + tid] = s;
    }
}

// ---------------- kernel 2a: chunk partial sums E, W[d] ---------------------
__global__ void partial_kernel()
{
    const int ch = blockIdx.x, bh = blockIdx.y, tid = threadIdx.x;   // 64 thr
    __shared__ float es[CT];
    __shared__ float ws[2];
    const float* sp = g_S + (size_t)bh * TT + ch * CT;
    float e = __expf(sp[tid]);
    es[tid] = e;
    float se = e;
#pragma unroll
    for (int o = 16; o; o >>= 1) se += __shfl_xor_sync(0xffffffffu, se, o);
    if ((tid & 31) == 0) ws[tid >> 5] = se;
    __syncthreads();
    if (tid == 0) g_E[bh * NC + ch] = ws[0] + ws[1];

    const float4* vp4 = (const float4*)(g_V + ((size_t)bh * 64 + tid) * 4096 + ch * CT);
    float w = 0.f;
#pragma unroll
    for (int j = 0; j < 16; j++) {
        float4 v = vp4[j];
        w = fmaf(es[4 * j],     v.x, w);
        w = fmaf(es[4 * j + 1], v.y, w);
        w = fmaf(es[4 * j + 2], v.z, w);
        w = fmaf(es[4 * j + 3], v.w, w);
    }
    g_W[((size_t)bh * NC + ch) * TD + tid] = w;
}

// ---------------- kernel 2b: exclusive scan of chunk aggregates -------------
// Batched: issue all 64 loads (full MLP), prefix in registers, store all.
__global__ void scanagg_kernel()
{
    const int bh = blockIdx.x, d = threadIdx.x;      // 64 threads
    float* wp = g_W + (size_t)bh * NC * TD + d;
    float v[NC];
#pragma unroll
    for (int c = 0; c < NC; c++) v[c] = wp[(size_t)c * TD];
    float aw = 0.f;
#pragma unroll
    for (int c = 0; c < NC; c++) { float t = v[c]; v[c] = aw; aw += t; }
#pragma unroll
    for (int c = 0; c < NC; c++) wp[(size_t)c * TD] = v[c];

    if (d == 0) {
        float* ep = g_E + bh * NC;
        float e[NC];
#pragma unroll
        for (int c = 0; c < NC; c++) e[c] = ep[c];
        float ae = 0.f;
#pragma unroll
        for (int c = 0; c < NC; c++) { float t = e[c]; e[c] = ae; ae += t; }
#pragma unroll
        for (int c = 0; c < NC; c++) ep[c] = e[c];
    }
}

// ---------------- kernel 2c: local scan + head-sum -> out -------------------
__global__ __launch_bounds__(1024) void final_kernel(float* __restrict__ out)
{
    __shared__ float es_s[1024], rc_s[1024], p_s[16 * 4 * 64], wtot[16];
    const int ch = blockIdx.x, b = blockIdx.y, tid = threadIdx.x;
    const int h = tid >> 6, t = tid & 63, lane = tid & 31, uh = (tid >> 5) & 1;
    const int bh = b * TH + h;

    float e = __expf(g_S[(size_t)bh * TT + ch * CT + t]);
    es_s[tid] = e;
    float p = e;
#pragma unroll
    for (int o = 1; o < 32; o <<= 1) {
        float x = __shfl_up_sync(0xffffffffu, p, o);
        if (lane >= o) p += x;
    }
    if (lane == 31 && uh == 0) wtot[h] = p;
    __syncthreads();
    float pref = p + (uh ? wtot[h] : 0.f);
    rc_s[tid] = 1.0f / (g_E[bh * NC + ch] + pref);
    __syncthreads();

    const int d = t;                                 // phase B mapping
    float a = g_W[((size_t)bh * NC + ch) * TD + d];  // exclusive prefix
    const float4* vp4 = (const float4*)(g_V + ((size_t)bh * 64 + d) * 4096 + ch * CT);
    float* outb = out + ((size_t)b * TT + ch * CT) * TD;

    for (int g4 = 0; g4 < 16; g4++) {
        float4 v = vp4[g4];
        a = fmaf(es_s[h * 64 + g4 * 4 + 0], v.x, a);
        p_s[(h * 4 + 0) * 64 + d] = a * rc_s[h * 64 + g4 * 4 + 0];
        a = fmaf(es_s[h * 64 + g4 * 4 + 1], v.y, a);
        p_s[(h * 4 + 1) * 64 + d] = a * rc_s[h * 64 + g4 * 4 + 1];
        a = fmaf(es_s[h * 64 + g4 * 4 + 2], v.z, a);
        p_s[(h * 4 + 2) * 64 + d] = a * rc_s[h * 64 + g4 * 4 + 2];
        a = fmaf(es_s[h * 64 + g4 * 4 + 3], v.w, a);
        p_s[(h * 4 + 3) * 64 + d] = a * rc_s[h * 64 + g4 * 4 + 3];
        __syncthreads();
        if (tid < 256) {
            int tt = tid >> 6, dd = tid & 63;
            float s = 0.f;
#pragma unroll
            for (int hh = 0; hh < 16; hh++) s += p_s[(hh * 4 + tt) * 64 + dd];
            outb[(size_t)(g4 * 4 + tt) * TD + dd] = s;
        }
        __syncthreads();
    }
}

// ---------------- launch ----------------------------------------------------
extern "C" void kernel_launch(void* const* d_in, const int* in_sizes, int n_in,
                              void* d_out, int out_size)
{
    const float* x = (const float*)d_in[0];   // inputs    [4,4096,1024]
    const float* w = (const float*)d_in[1];   // kv_kernel [1024,16,64,2]
    const float* q = (const float*)d_in[2];   // q_kernel  [16,64]
    float* out = (float*)d_out;               // [4,4096,64] f32

    cvt_w_kernel<<<2048, 256>>>((const float4*)w);

    cudaFuncSetAttribute(gemm_kernel,
                         cudaFuncAttributeMaxDynamicSharedMemorySize, 155648);
    gemm_kernel<<<dim3(16, 64), 512, 155648>>>(x, q);

    partial_kernel<<<dim3(NC, 64), CT>>>();
    scanagg_kernel<<<64, TD>>>();
    final_kernel<<<dim3(NC, TB), 1024>>>(out);
}